// round 9
// baseline (speedup 1.0000x reference)
#include <cuda_runtime.h>
#include <cuda_fp16.h>
#include <cstdint>
#include <cstddef>

#define Vv 10000
#define Tt 5
#define Ee 256
#define Hh 512
#define Bb 64
#define Ss 512
#define Gg 2048

__device__ float g_P[(size_t)Vv * 4096];
__device__ float g_xg[(size_t)2 * Ss * Gg * Bb];          /* [d][s][g][b] */
__device__ __half g_H16[2 * 2 * 32768];                   /* [d][par][k*64+b swizzled] */
__device__ float g_lstm[(size_t)Ss * 2 * Hh * Bb];        /* [s][h2][b] */
__device__ float g_em[(size_t)Bb * Ss * Tt];
__device__ int   g_xT[Ss * Bb];
__device__ float g_scores[Bb];
__device__ volatile unsigned g_flag[128];                 /* [d*64+mblk] epoch */

__device__ __forceinline__ uint32_t smem_u32(const void* p) {
    uint32_t a;
    asm("{ .reg .u64 t; cvta.to.shared.u64 t, %1; cvt.u32.u64 %0, t; }" : "=r"(a) : "l"(p));
    return a;
}
#define LDSM4(r0,r1,r2,r3,ad) asm volatile( \
    "ldmatrix.sync.aligned.m8n8.x4.shared.b16 {%0,%1,%2,%3}, [%4];" \
    : "=r"(r0),"=r"(r1),"=r"(r2),"=r"(r3) : "r"(ad))
#define LDSM4T(r0,r1,r2,r3,ad) asm volatile( \
    "ldmatrix.sync.aligned.m8n8.x4.trans.shared.b16 {%0,%1,%2,%3}, [%4];" \
    : "=r"(r0),"=r"(r1),"=r"(r2),"=r"(r3) : "r"(ad))
#define MMA16(d,a0,a1,a2,a3,b0,b1) asm volatile( \
    "mma.sync.aligned.m16n8k16.row.col.f32.f16.f16.f32 " \
    "{%0,%1,%2,%3}, {%4,%5,%6,%7}, {%8,%9}, {%0,%1,%2,%3};" \
    : "+f"((d)[0]),"+f"((d)[1]),"+f"((d)[2]),"+f"((d)[3]) \
    : "r"(a0),"r"(a1),"r"(a2),"r"(a3),"r"(b0),"r"(b1))

/* ---- prep ---- */
__global__ void prep_kernel(const int* __restrict__ x)
{
    int i = blockIdx.x * blockDim.x + threadIdx.x;       /* 131072 */
    if (i < 65536) ((unsigned*)g_H16)[i] = 0;
    if (i < Ss * Bb) { int s = i >> 6, b = i & 63; g_xT[i] = x[b * Ss + s]; }
    if (i < 128) g_flag[i] = 0;
}

/* ---- vocab projection: P = emb @ Wih^T + b ---- */
__global__ void __launch_bounds__(256) proj_kernel(
    const float* __restrict__ emb,
    const float* __restrict__ Wf, const float* __restrict__ bf,
    const float* __restrict__ Wb, const float* __restrict__ bb)
{
    __shared__ float sA[32 * 68], sB[32 * 68];
    const int v0 = blockIdx.x * 64, g0 = blockIdx.y * 64;
    const float* W  = (g0 < 2048) ? Wf : Wb;
    const float* bi = (g0 < 2048) ? bf : bb;
    const int gb = (g0 < 2048) ? g0 : g0 - 2048;
    const int tid = threadIdx.x, tx = tid & 15, ty = tid >> 4;
    float acc[4][4];
#pragma unroll
    for (int i = 0; i < 4; i++)
#pragma unroll
        for (int j = 0; j < 4; j++) acc[i][j] = 0.f;
    for (int e0 = 0; e0 < Ee; e0 += 32) {
#pragma unroll
        for (int it = 0; it < 2; it++) {
            int lin = tid + it * 256, row = lin >> 3, q = lin & 7;
            int v = v0 + row; if (v >= Vv) v = Vv - 1;
            float4 a = *(const float4*)&emb[(size_t)v * Ee + e0 + q * 4];
            sA[(q*4+0)*68+row]=a.x; sA[(q*4+1)*68+row]=a.y; sA[(q*4+2)*68+row]=a.z; sA[(q*4+3)*68+row]=a.w;
            float4 w = *(const float4*)&W[(size_t)(gb + row) * Ee + e0 + q * 4];
            sB[(q*4+0)*68+row]=w.x; sB[(q*4+1)*68+row]=w.y; sB[(q*4+2)*68+row]=w.z; sB[(q*4+3)*68+row]=w.w;
        }
        __syncthreads();
#pragma unroll
        for (int e = 0; e < 32; e++) {
            float4 a4 = *(const float4*)&sA[e * 68 + tx * 4];
            float4 b4 = *(const float4*)&sB[e * 68 + ty * 4];
            float av[4] = {a4.x, a4.y, a4.z, a4.w}, bv[4] = {b4.x, b4.y, b4.z, b4.w};
#pragma unroll
            for (int i = 0; i < 4; i++)
#pragma unroll
                for (int j = 0; j < 4; j++) acc[i][j] += av[i] * bv[j];
        }
        __syncthreads();
    }
#pragma unroll
    for (int i = 0; i < 4; i++) {
        int v = v0 + tx * 4 + i;
        if (v < Vv)
#pragma unroll
            for (int j = 0; j < 4; j++)
                g_P[(size_t)v * 4096 + g0 + ty * 4 + j] = acc[i][j] + bi[gb + ty * 4 + j];
    }
}

/* ---- gather+transpose: xg[d][s][g][b] = P[x[b][s]][d*2048+g] ---- */
__global__ void gather_kernel(const int* __restrict__ x)
{
    __shared__ float tile[64 * 68];
    int sb = blockIdx.x, s = sb >> 1, d = sb & 1, t = threadIdx.x;
    int lb = t & 63, lq = t >> 6, wg = t >> 2, wq = t & 3;
    int tok = x[lb * Ss + s];
    const float* src = g_P + (size_t)tok * 4096 + d * 2048;
    float* dst = g_xg + ((size_t)(d * Ss + s)) * Gg * Bb;
    for (int g0 = 0; g0 < Gg; g0 += 64) {
#pragma unroll
        for (int j = 0; j < 4; j++) {
            int col = lq * 16 + j * 4;
            *(float4*)&tile[lb * 68 + col] = __ldg((const float4*)&src[g0 + col]);
        }
        __syncthreads();
        float o[16];
#pragma unroll
        for (int i = 0; i < 16; i++) o[i] = tile[(wq * 16 + i) * 68 + wg];
        float4* ob = (float4*)&dst[(size_t)(g0 + wg) * Bb + wq * 16];
#pragma unroll
        for (int i = 0; i < 4; i++) ob[i] = ((float4*)o)[i];
        __syncthreads();
    }
}

/* ---- persistent BiLSTM via mma.sync f16 ----
   128 blocks: d(2) x m(64). Block: 8 units = 32 gate rows x 64 b, K=512.
   Warp (8): wm = wid&1 (m16), wn = wid>>1 (n16), full K.
   A fp16 resident; B fp16 staged in two 32KB chunks (chunk1 L2 traffic
   hidden under chunk0 GEMM). Distributed write-flags replace barrier. */
#define OFF_AH 0
#define OFF_B  32768
#define OFF_G  98304
#define GP 66
#define LSTM_SMEM (OFF_G + 32 * GP * 4)

__device__ __forceinline__ float sigm(float x) { return 1.f / (1.f + expf(-x)); }

__global__ void __launch_bounds__(256, 1) lstm_kernel(
    const float* __restrict__ Whh_f, const float* __restrict__ Whh_b)
{
    extern __shared__ char smem[];
    const uint32_t sb = smem_u32(smem);
    float* gate_s = (float*)(smem + OFF_G);
    const int t = threadIdx.x, lane = t & 31, wid = t >> 5;
    const int d = blockIdx.x >> 6, mblk = blockIdx.x & 63;
    const int u0 = mblk * 8;
    const float* Whh = d ? Whh_b : Whh_f;

    /* A fp16 into swizzled smem: row r = type*8+u, 1KB rows */
    for (int i = t; i < 32 * 512; i += 256) {
        int r = i >> 9, k = i & 511;
        float w = Whh[(size_t)((r >> 3) * Hh + u0 + (r & 7)) * Hh + k];
        uint32_t off = (uint32_t)r * 1024 + ((((k >> 3) ^ (r & 7))) << 4) + (k & 7) * 2;
        *(__half*)(smem + OFF_AH + off) = __float2half_rn(w);
    }

    /* GEMM role constants */
    const int wm = wid & 1, wn = wid >> 1;
    const int m_l = wm * 16 + (lane & 15);
    const int kh  = lane >> 4;
    const int me7 = m_l & 7;
    const uint32_t aBH = sb + OFF_AH + m_l * 1024;
    const int k_ln = lane & 15;
    const int n_l  = wn * 16 + (lane >> 4) * 8;
    const uint32_t bcol = (uint32_t)(((n_l >> 3) ^ (k_ln & 7)) << 4);
    const uint32_t bBH = sb + OFF_B + k_ln * 128 + bcol;

    /* cell role: units cu_u, cu_u+4; batch cu_b */
    const int cu_u = t >> 6, cu_b = t & 63;
    float cst[2] = {0.f, 0.f}, hst[2] = {0.f, 0.f};
    __syncthreads();

    for (int step = 0; step < Ss; step++) {
        const int s = d ? (Ss - 1 - step) : step;
        const int p = step & 1;

        /* prefetch xg + mask (independent of h) */
        float xr[8];
        {
            const float* xbase = g_xg + ((size_t)(d * Ss + s)) * Gg * Bb + cu_b;
#pragma unroll
            for (int cc = 0; cc < 2; cc++)
#pragma unroll
                for (int ty = 0; ty < 4; ty++)
                    xr[cc * 4 + ty] = __ldg(xbase + (size_t)(ty * Hh + u0 + cu_u + cc * 4) * Bb);
        }
        const int msk = g_xT[s * Bb + cu_b];

        /* wait until all 64 producer blocks of this dir finished step-1 */
        if (t < 64) { while (g_flag[d * 64 + t] < (unsigned)step) { } }
        __syncthreads();

        /* issue all B loads (both 32KB chunks in flight) */
        float4 c0[8], c1[8];
        {
            const float4* srcp = (const float4*)(g_H16 + (size_t)(d * 2 + p) * 32768);
#pragma unroll
            for (int i = 0; i < 8; i++) c0[i] = __ldcg(srcp + t + i * 256);
#pragma unroll
            for (int i = 0; i < 8; i++) c1[i] = __ldcg(srcp + 2048 + t + i * 256);
        }
        float4* dstp = (float4*)(smem + OFF_B);
#pragma unroll
        for (int i = 0; i < 8; i++) dstp[t + i * 256] = c0[i];
        __syncthreads();

        float d0[4] = {0.f,0.f,0.f,0.f}, d1[4] = {0.f,0.f,0.f,0.f};
        /* GEMM chunk0: k = 0..255 */
#pragma unroll 4
        for (int ks = 0; ks < 16; ks++) {
            uint32_t ah0,ah1,ah2,ah3, bh0,bh1,bh2,bh3;
            uint32_t asw = (uint32_t)(((2 * ks + kh) ^ me7) << 4);
            LDSM4(ah0,ah1,ah2,ah3, aBH + asw);
            LDSM4T(bh0,bh1,bh2,bh3, bBH + ks * 2048);
            MMA16(d0, ah0,ah1,ah2,ah3, bh0,bh1);
            MMA16(d1, ah0,ah1,ah2,ah3, bh2,bh3);
        }
        /* stage chunk1, GEMM k = 256..511 */
#pragma unroll
        for (int i = 0; i < 8; i++) dstp[2048 + t + i * 256] = c1[i];
        __syncthreads();
#pragma unroll 4
        for (int ks = 16; ks < 32; ks++) {
            uint32_t ah0,ah1,ah2,ah3, bh0,bh1,bh2,bh3;
            uint32_t asw = (uint32_t)(((2 * ks + kh) ^ me7) << 4);
            LDSM4(ah0,ah1,ah2,ah3, aBH + asw);
            LDSM4T(bh0,bh1,bh2,bh3, bBH + ks * 2048);
            MMA16(d0, ah0,ah1,ah2,ah3, bh0,bh1);
            MMA16(d1, ah0,ah1,ah2,ah3, bh2,bh3);
        }
        /* write D to gates smem */
        {
            int g = lane >> 2, tg = lane & 3;
            int r0 = wm * 16 + g, c0i = wn * 16 + tg * 2;
            gate_s[r0 * GP + c0i]           = d0[0];
            gate_s[r0 * GP + c0i + 1]       = d0[1];
            gate_s[(r0 + 8) * GP + c0i]     = d0[2];
            gate_s[(r0 + 8) * GP + c0i + 1] = d0[3];
            gate_s[r0 * GP + c0i + 8]           = d1[0];
            gate_s[r0 * GP + c0i + 9]           = d1[1];
            gate_s[(r0 + 8) * GP + c0i + 8]     = d1[2];
            gate_s[(r0 + 8) * GP + c0i + 9]     = d1[3];
        }
        __syncthreads();

        /* cell update: 2 cells per thread */
        __half* bhi = g_H16 + (size_t)(d * 2 + (1 - p)) * 32768;
#pragma unroll
        for (int cc = 0; cc < 2; cc++) {
            int u = cu_u + cc * 4;
            float ig = gate_s[(0 * 8 + u) * GP + cu_b] + xr[cc * 4 + 0];
            float fg = gate_s[(1 * 8 + u) * GP + cu_b] + xr[cc * 4 + 1];
            float gg = gate_s[(2 * 8 + u) * GP + cu_b] + xr[cc * 4 + 2];
            float og = gate_s[(3 * 8 + u) * GP + cu_b] + xr[cc * 4 + 3];
            float cn = sigm(fg) * cst[cc] + sigm(ig) * tanhf(gg);
            float hn = sigm(og) * tanhf(cn);
            float outv;
            if (msk != 0) { cst[cc] = cn; hst[cc] = hn; outv = hn; }
            else outv = 0.f;
            int ku = u0 + u;
            uint32_t off = (uint32_t)ku * 128 + (((cu_b >> 3) ^ (ku & 7)) << 4) + (cu_b & 7) * 2;
            *(__half*)((char*)bhi + off) = __float2half_rn(hst[cc]);
            g_lstm[((size_t)s * 2 * Hh + d * Hh + ku) * Bb + cu_b] = outv;
        }

        /* publish: all writes visible, then bump this block's flag */
        __threadfence();
        __syncthreads();
        if (t == 0) g_flag[d * 64 + mblk] = (unsigned)(step + 1);
    }
}

/* ---- emissions ---- */
__global__ void emis_kernel(const float* __restrict__ Wlin,
                            const float* __restrict__ blin)
{
    __shared__ float sW[Tt * 2 * Hh];
    int s = blockIdx.x, t = threadIdx.x;
    for (int i = t; i < Tt * 2 * Hh; i += 320) sW[i] = Wlin[i];
    __syncthreads();
    int tag = t >> 6, b = t & 63;
    const float* lp = g_lstm + (size_t)s * 2 * Hh * Bb + b;
    const float* wp = sW + tag * 2 * Hh;
    float acc = 0.f;
#pragma unroll 8
    for (int h = 0; h < 2 * Hh; h++) acc += __ldg(lp + (size_t)h * Bb) * wp[h];
    g_em[((size_t)b * Ss + s) * Tt + tag] = acc + blin[tag];
}

/* ---- CRF ---- */
__global__ void crf_kernel(const int* __restrict__ tags,
                           const int* __restrict__ lengths,
                           const float* __restrict__ trans,
                           const float* __restrict__ start_t,
                           const float* __restrict__ end_t)
{
    int b = blockIdx.x, lane = threadIdx.x;
    const int* tg = tags + (size_t)b * Ss;
    int len = lengths[b];
    float num = 0.f;
    for (int s = lane; s < len; s += 32) {
        int tc = tg[s];
        float e = g_em[((size_t)b * Ss + s) * Tt + tc];
        if (s == 0) num += start_t[tc] + e;
        else        num += trans[tg[s - 1] * Tt + tc] + e;
    }
#pragma unroll
    for (int o = 16; o; o >>= 1) num += __shfl_down_sync(0xffffffffu, num, o);
    num = __shfl_sync(0xffffffffu, num, 0);
    if (lane == 0) num += end_t[tg[len - 1]];
    num = __shfl_sync(0xffffffffu, num, 0);

    int lt = lane < 5 ? lane : 0;
    float trc[5];
#pragma unroll
    for (int i = 0; i < 5; i++) trc[i] = trans[i * Tt + lt];
    float alpha = start_t[lt] + g_em[((size_t)b * Ss) * Tt + lt];
    for (int s = 1; s < len; s++) {
        float av[5];
#pragma unroll
        for (int i = 0; i < 5; i++) av[i] = __shfl_sync(0xffffffffu, alpha, i) + trc[i];
        float mx = av[0];
#pragma unroll
        for (int i = 1; i < 5; i++) mx = fmaxf(mx, av[i]);
        float ssum = 0.f;
#pragma unroll
        for (int i = 0; i < 5; i++) ssum += expf(av[i] - mx);
        float an = mx + logf(ssum) + g_em[((size_t)b * Ss + s) * Tt + lt];
        if (lane < 5) alpha = an;
    }
    float v = (lane < 5) ? alpha + end_t[lane] : -3.0e38f;
    float mx = v;
#pragma unroll
    for (int o = 16; o; o >>= 1) mx = fmaxf(mx, __shfl_xor_sync(0xffffffffu, mx, o));
    float e = (lane < 5) ? expf(v - mx) : 0.f;
#pragma unroll
    for (int o = 16; o; o >>= 1) e += __shfl_xor_sync(0xffffffffu, e, o);
    if (lane == 0) g_scores[b] = mx + logf(e) - num;
}

__global__ void finish_kernel(float* __restrict__ out)
{
    int t = threadIdx.x;
    float v = g_scores[t] + g_scores[t + 32];
#pragma unroll
    for (int o = 16; o; o >>= 1) v += __shfl_down_sync(0xffffffffu, v, o);
    if (t == 0) out[0] = v * (1.f / 64.f);
}

extern "C" void kernel_launch(void* const* d_in, const int* in_sizes, int n_in,
                              void* d_out, int out_size)
{
    const int*   x       = (const int*)d_in[0];
    const int*   tags    = (const int*)d_in[1];
    const int*   lengths = (const int*)d_in[2];
    const float* emb     = (const float*)d_in[3];
    const float* Wih_f   = (const float*)d_in[4];
    const float* Whh_f   = (const float*)d_in[5];
    const float* b_f     = (const float*)d_in[6];
    const float* Wih_b   = (const float*)d_in[7];
    const float* Whh_b   = (const float*)d_in[8];
    const float* b_b     = (const float*)d_in[9];
    const float* Wlin    = (const float*)d_in[10];
    const float* blin    = (const float*)d_in[11];
    const float* trans   = (const float*)d_in[12];
    const float* start_t = (const float*)d_in[13];
    const float* end_t   = (const float*)d_in[14];
    float* out = (float*)d_out;

    cudaFuncSetAttribute(lstm_kernel,
                         cudaFuncAttributeMaxDynamicSharedMemorySize, LSTM_SMEM);

    prep_kernel<<<512, 256>>>(x);
    proj_kernel<<<dim3((Vv + 63) / 64, 4096 / 64), 256>>>(emb, Wih_f, b_f, Wih_b, b_b);
    gather_kernel<<<2 * Ss, 256>>>(x);
    lstm_kernel<<<128, 256, LSTM_SMEM>>>(Whh_f, Whh_b);
    emis_kernel<<<Ss, 320>>>(Wlin, blin);
    crf_kernel<<<Bb, 32>>>(tags, lengths, trans, start_t, end_t);
    finish_kernel<<<1, 32>>>(out);
}

// round 10
// speedup vs baseline: 1.1158x; 1.1158x over previous
#include <cuda_runtime.h>
#include <cuda_fp16.h>
#include <cstdint>
#include <cstddef>

#define Vv 10000
#define Tt 5
#define Ee 256
#define Hh 512
#define Bb 64
#define Ss 512
#define Gg 2048

__device__ float g_P[(size_t)Vv * 4096];
__device__ __half g_emb16[(size_t)Vv * Ee];
__device__ __half g_W16T[(size_t)2 * Ee * Gg];            /* [d][k][g] */
__device__ float g_xg[(size_t)2 * Ss * Gg * Bb];          /* [d][s][g][b] */
__device__ __half g_H16[2 * 2 * 32768];                   /* [d][par][k*64+b swizzled] */
__device__ float g_lstm[(size_t)Ss * 2 * Hh * Bb];        /* [s][h2][b] */
__device__ float g_em[(size_t)Bb * Ss * Tt];
__device__ int   g_xT[Ss * Bb];
__device__ float g_scores[Bb];
__device__ volatile unsigned g_flag[128];                 /* [d*64+mblk] epoch */

__device__ __forceinline__ uint32_t smem_u32(const void* p) {
    uint32_t a;
    asm("{ .reg .u64 t; cvta.to.shared.u64 t, %1; cvt.u32.u64 %0, t; }" : "=r"(a) : "l"(p));
    return a;
}
#define LDSM4(r0,r1,r2,r3,ad) asm volatile( \
    "ldmatrix.sync.aligned.m8n8.x4.shared.b16 {%0,%1,%2,%3}, [%4];" \
    : "=r"(r0),"=r"(r1),"=r"(r2),"=r"(r3) : "r"(ad))
#define LDSM4T(r0,r1,r2,r3,ad) asm volatile( \
    "ldmatrix.sync.aligned.m8n8.x4.trans.shared.b16 {%0,%1,%2,%3}, [%4];" \
    : "=r"(r0),"=r"(r1),"=r"(r2),"=r"(r3) : "r"(ad))
#define MMA16(d,a0,a1,a2,a3,b0,b1) asm volatile( \
    "mma.sync.aligned.m16n8k16.row.col.f32.f16.f16.f32 " \
    "{%0,%1,%2,%3}, {%4,%5,%6,%7}, {%8,%9}, {%0,%1,%2,%3};" \
    : "+f"((d)[0]),"+f"((d)[1]),"+f"((d)[2]),"+f"((d)[3]) \
    : "r"(a0),"r"(a1),"r"(a2),"r"(a3),"r"(b0),"r"(b1))

/* ---- prep ---- */
__global__ void prep_kernel(const int* __restrict__ x)
{
    int i = blockIdx.x * blockDim.x + threadIdx.x;       /* 131072 */
    if (i < 65536) ((unsigned*)g_H16)[i] = 0;
    if (i < Ss * Bb) { int s = i >> 6, b = i & 63; g_xT[i] = x[b * Ss + s]; }
    if (i < 128) g_flag[i] = 0;
}

/* ---- fp16 conversions: emb16[v][e], W16T[d][k][g] ---- */
__global__ void conv_kernel(const float* __restrict__ emb,
                            const float* __restrict__ Wf,
                            const float* __restrict__ Wb)
{
    int i = blockIdx.x * blockDim.x + threadIdx.x;       /* 2,560,000 */
    if (i < Vv * Ee) g_emb16[i] = __float2half_rn(emb[i]);
    if (i < 2 * Ee * Gg) {                               /* i = (d*256+k)*2048+g */
        int d = i >> 19;
        int r = i & 524287, k = r >> 11, g = r & 2047;
        const float* W = d ? Wb : Wf;
        g_W16T[i] = __float2half_rn(W[(size_t)g * Ee + k]);
    }
}

/* ---- tensor proj: P[v][g] = emb[v]·Wih^T[g] + b, 128x128 tiles, K=256 ----
   smem: A 64KB ([128 v rows][512B], swizzled), B 64KB ([256 k rows][256B]). */
#define PJ_A 0
#define PJ_B 65536
#define PROJ_SMEM 131072
__global__ void __launch_bounds__(256) proj_kernel(
    const float* __restrict__ bf, const float* __restrict__ bb)
{
    extern __shared__ char smem[];
    const uint32_t sbs = smem_u32(smem);
    const int t = threadIdx.x, lane = t & 31, wid = t >> 5;
    const int v0 = blockIdx.x * 128, g0 = blockIdx.y * 128;   /* g0 in 0..4095 */
    const int dir = g0 >> 11, gb0 = g0 & 2047;
    const float* bip = dir ? bb : bf;

    /* stage A (emb16 rows, clamped) */
    for (int i = t; i < 8192; i += 256) {
        int r = i >> 5, c = i & 31;
        int v = v0 + r; if (v >= Vv) v = Vv - 1;
        float4 val = *(const float4*)(g_emb16 + (size_t)v * Ee + c * 8);
        *(float4*)(smem + PJ_A + r * 512 + (((c ^ (r & 7))) << 4)) = val;
    }
    /* stage B (W16T rows k, g-slice) */
    for (int i = t; i < 4096; i += 256) {
        int k = i >> 4, c = i & 15;
        float4 val = *(const float4*)(g_W16T + ((size_t)(dir * Ee + k)) * Gg + gb0 + c * 8);
        *(float4*)(smem + PJ_B + k * 256 + (((c ^ (k & 7))) << 4)) = val;
    }
    __syncthreads();

    const int m_l = wid * 16 + (lane & 15);
    const int kh  = lane >> 4;
    const int k_ln = lane & 15;
    const uint32_t aB = sbs + PJ_A + m_l * 512;
    float D[16][4];
#pragma unroll
    for (int i = 0; i < 16; i++)
#pragma unroll
        for (int j = 0; j < 4; j++) D[i][j] = 0.f;

#pragma unroll 2
    for (int ks = 0; ks < 16; ks++) {
        uint32_t a0,a1,a2,a3;
        LDSM4(a0,a1,a2,a3, aB + (uint32_t)(((2 * ks + kh) ^ (m_l & 7)) << 4));
        uint32_t brow = sbs + PJ_B + (ks * 16 + k_ln) * 256;
#pragma unroll
        for (int nt = 0; nt < 8; nt++) {
            uint32_t b0,b1,b2,b3;
            LDSM4T(b0,b1,b2,b3, brow + (uint32_t)(((nt * 2 + kh) ^ (k_ln & 7)) << 4));
            MMA16(D[nt * 2],     a0,a1,a2,a3, b0,b1);
            MMA16(D[nt * 2 + 1], a0,a1,a2,a3, b2,b3);
        }
    }
    /* epilogue: add bias, store fp32 */
    int vr = v0 + wid * 16 + (lane >> 2);
    int tg = lane & 3;
#pragma unroll
    for (int nt = 0; nt < 16; nt++) {
        int gc = g0 + nt * 8 + tg * 2;
        float b0v = __ldg(bip + (gc & 2047));
        float b1v = __ldg(bip + ((gc + 1) & 2047));
        if (vr < Vv)
            *(float2*)&g_P[(size_t)vr * 4096 + gc] = make_float2(D[nt][0] + b0v, D[nt][1] + b1v);
        if (vr + 8 < Vv)
            *(float2*)&g_P[(size_t)(vr + 8) * 4096 + gc] = make_float2(D[nt][2] + b0v, D[nt][3] + b1v);
    }
}

/* ---- gather+transpose: xg[d][s][g][b] = P[x[b][s]][d*2048+g] ---- */
__global__ void gather_kernel(const int* __restrict__ x)
{
    __shared__ float tile[64 * 68];
    int sb = blockIdx.x, s = sb >> 1, d = sb & 1, t = threadIdx.x;
    int lb = t & 63, lq = t >> 6, wg = t >> 2, wq = t & 3;
    int tok = x[lb * Ss + s];
    const float* src = g_P + (size_t)tok * 4096 + d * 2048;
    float* dst = g_xg + ((size_t)(d * Ss + s)) * Gg * Bb;
    for (int g0 = 0; g0 < Gg; g0 += 64) {
#pragma unroll
        for (int j = 0; j < 4; j++) {
            int col = lq * 16 + j * 4;
            *(float4*)&tile[lb * 68 + col] = __ldg((const float4*)&src[g0 + col]);
        }
        __syncthreads();
        float o[16];
#pragma unroll
        for (int i = 0; i < 16; i++) o[i] = tile[(wq * 16 + i) * 68 + wg];
        float4* ob = (float4*)&dst[(size_t)(g0 + wg) * Bb + wq * 16];
#pragma unroll
        for (int i = 0; i < 4; i++) ob[i] = ((float4*)o)[i];
        __syncthreads();
    }
}

/* ---- persistent BiLSTM via mma.sync f16 (unchanged from R9) ---- */
#define OFF_AH 0
#define OFF_B  32768
#define OFF_G  98304
#define GP 66
#define LSTM_SMEM (OFF_G + 32 * GP * 4)

__device__ __forceinline__ float sigm(float x) { return 1.f / (1.f + expf(-x)); }

__global__ void __launch_bounds__(256, 1) lstm_kernel(
    const float* __restrict__ Whh_f, const float* __restrict__ Whh_b)
{
    extern __shared__ char smem[];
    const uint32_t sb = smem_u32(smem);
    float* gate_s = (float*)(smem + OFF_G);
    const int t = threadIdx.x, lane = t & 31, wid = t >> 5;
    const int d = blockIdx.x >> 6, mblk = blockIdx.x & 63;
    const int u0 = mblk * 8;
    const float* Whh = d ? Whh_b : Whh_f;

    for (int i = t; i < 32 * 512; i += 256) {
        int r = i >> 9, k = i & 511;
        float w = Whh[(size_t)((r >> 3) * Hh + u0 + (r & 7)) * Hh + k];
        uint32_t off = (uint32_t)r * 1024 + ((((k >> 3) ^ (r & 7))) << 4) + (k & 7) * 2;
        *(__half*)(smem + OFF_AH + off) = __float2half_rn(w);
    }

    const int wm = wid & 1, wn = wid >> 1;
    const int m_l = wm * 16 + (lane & 15);
    const int kh  = lane >> 4;
    const int me7 = m_l & 7;
    const uint32_t aBH = sb + OFF_AH + m_l * 1024;
    const int k_ln = lane & 15;
    const int n_l  = wn * 16 + (lane >> 4) * 8;
    const uint32_t bcol = (uint32_t)(((n_l >> 3) ^ (k_ln & 7)) << 4);
    const uint32_t bBH = sb + OFF_B + k_ln * 128 + bcol;

    const int cu_u = t >> 6, cu_b = t & 63;
    float cst[2] = {0.f, 0.f}, hst[2] = {0.f, 0.f};
    __syncthreads();

    for (int step = 0; step < Ss; step++) {
        const int s = d ? (Ss - 1 - step) : step;
        const int p = step & 1;

        float xr[8];
        {
            const float* xbase = g_xg + ((size_t)(d * Ss + s)) * Gg * Bb + cu_b;
#pragma unroll
            for (int cc = 0; cc < 2; cc++)
#pragma unroll
                for (int ty = 0; ty < 4; ty++)
                    xr[cc * 4 + ty] = __ldg(xbase + (size_t)(ty * Hh + u0 + cu_u + cc * 4) * Bb);
        }
        const int msk = g_xT[s * Bb + cu_b];

        if (t < 64) { while (g_flag[d * 64 + t] < (unsigned)step) { } }
        __syncthreads();

        float4 c0[8], c1[8];
        {
            const float4* srcp = (const float4*)(g_H16 + (size_t)(d * 2 + p) * 32768);
#pragma unroll
            for (int i = 0; i < 8; i++) c0[i] = __ldcg(srcp + t + i * 256);
#pragma unroll
            for (int i = 0; i < 8; i++) c1[i] = __ldcg(srcp + 2048 + t + i * 256);
        }
        float4* dstp = (float4*)(smem + OFF_B);
#pragma unroll
        for (int i = 0; i < 8; i++) dstp[t + i * 256] = c0[i];
        __syncthreads();

        float d0[4] = {0.f,0.f,0.f,0.f}, d1[4] = {0.f,0.f,0.f,0.f};
#pragma unroll 4
        for (int ks = 0; ks < 16; ks++) {
            uint32_t ah0,ah1,ah2,ah3, bh0,bh1,bh2,bh3;
            uint32_t asw = (uint32_t)(((2 * ks + kh) ^ me7) << 4);
            LDSM4(ah0,ah1,ah2,ah3, aBH + asw);
            LDSM4T(bh0,bh1,bh2,bh3, bBH + ks * 2048);
            MMA16(d0, ah0,ah1,ah2,ah3, bh0,bh1);
            MMA16(d1, ah0,ah1,ah2,ah3, bh2,bh3);
        }
#pragma unroll
        for (int i = 0; i < 8; i++) dstp[2048 + t + i * 256] = c1[i];
        __syncthreads();
#pragma unroll 4
        for (int ks = 16; ks < 32; ks++) {
            uint32_t ah0,ah1,ah2,ah3, bh0,bh1,bh2,bh3;
            uint32_t asw = (uint32_t)(((2 * ks + kh) ^ me7) << 4);
            LDSM4(ah0,ah1,ah2,ah3, aBH + asw);
            LDSM4T(bh0,bh1,bh2,bh3, bBH + ks * 2048);
            MMA16(d0, ah0,ah1,ah2,ah3, bh0,bh1);
            MMA16(d1, ah0,ah1,ah2,ah3, bh2,bh3);
        }
        {
            int g = lane >> 2, tg = lane & 3;
            int r0 = wm * 16 + g, c0i = wn * 16 + tg * 2;
            gate_s[r0 * GP + c0i]           = d0[0];
            gate_s[r0 * GP + c0i + 1]       = d0[1];
            gate_s[(r0 + 8) * GP + c0i]     = d0[2];
            gate_s[(r0 + 8) * GP + c0i + 1] = d0[3];
            gate_s[r0 * GP + c0i + 8]           = d1[0];
            gate_s[r0 * GP + c0i + 9]           = d1[1];
            gate_s[(r0 + 8) * GP + c0i + 8]     = d1[2];
            gate_s[(r0 + 8) * GP + c0i + 9]     = d1[3];
        }
        __syncthreads();

        __half* bhi = g_H16 + (size_t)(d * 2 + (1 - p)) * 32768;
#pragma unroll
        for (int cc = 0; cc < 2; cc++) {
            int u = cu_u + cc * 4;
            float ig = gate_s[(0 * 8 + u) * GP + cu_b] + xr[cc * 4 + 0];
            float fg = gate_s[(1 * 8 + u) * GP + cu_b] + xr[cc * 4 + 1];
            float gg = gate_s[(2 * 8 + u) * GP + cu_b] + xr[cc * 4 + 2];
            float og = gate_s[(3 * 8 + u) * GP + cu_b] + xr[cc * 4 + 3];
            float cn = sigm(fg) * cst[cc] + sigm(ig) * tanhf(gg);
            float hn = sigm(og) * tanhf(cn);
            float outv;
            if (msk != 0) { cst[cc] = cn; hst[cc] = hn; outv = hn; }
            else outv = 0.f;
            int ku = u0 + u;
            uint32_t off = (uint32_t)ku * 128 + (((cu_b >> 3) ^ (ku & 7)) << 4) + (cu_b & 7) * 2;
            *(__half*)((char*)bhi + off) = __float2half_rn(hst[cc]);
            g_lstm[((size_t)s * 2 * Hh + d * Hh + ku) * Bb + cu_b] = outv;
        }

        __threadfence();
        __syncthreads();
        if (t == 0) g_flag[d * 64 + mblk] = (unsigned)(step + 1);
    }
}

/* ---- emissions ---- */
__global__ void emis_kernel(const float* __restrict__ Wlin,
                            const float* __restrict__ blin)
{
    __shared__ float sW[Tt * 2 * Hh];
    int s = blockIdx.x, t = threadIdx.x;
    for (int i = t; i < Tt * 2 * Hh; i += 320) sW[i] = Wlin[i];
    __syncthreads();
    int tag = t >> 6, b = t & 63;
    const float* lp = g_lstm + (size_t)s * 2 * Hh * Bb + b;
    const float* wp = sW + tag * 2 * Hh;
    float acc = 0.f;
#pragma unroll 8
    for (int h = 0; h < 2 * Hh; h++) acc += __ldg(lp + (size_t)h * Bb) * wp[h];
    g_em[((size_t)b * Ss + s) * Tt + tag] = acc + blin[tag];
}

/* ---- CRF (emissions staged in smem) ---- */
__global__ void crf_kernel(const int* __restrict__ tags,
                           const int* __restrict__ lengths,
                           const float* __restrict__ trans,
                           const float* __restrict__ start_t,
                           const float* __restrict__ end_t)
{
    __shared__ float sem[Ss * Tt];
    int b = blockIdx.x, lane = threadIdx.x;
    const int* tg = tags + (size_t)b * Ss;
    int len = lengths[b];

    for (int i = lane; i < (Ss * Tt) / 4; i += 32)
        ((float4*)sem)[i] = __ldg((const float4*)(g_em + (size_t)b * Ss * Tt) + i);
    __syncwarp();

    float num = 0.f;
    for (int s = lane; s < len; s += 32) {
        int tc = tg[s];
        float e = sem[s * Tt + tc];
        if (s == 0) num += start_t[tc] + e;
        else        num += trans[tg[s - 1] * Tt + tc] + e;
    }
#pragma unroll
    for (int o = 16; o; o >>= 1) num += __shfl_down_sync(0xffffffffu, num, o);
    num = __shfl_sync(0xffffffffu, num, 0);
    if (lane == 0) num += end_t[tg[len - 1]];
    num = __shfl_sync(0xffffffffu, num, 0);

    int lt = lane < 5 ? lane : 0;
    float trc[5];
#pragma unroll
    for (int i = 0; i < 5; i++) trc[i] = trans[i * Tt + lt];
    float alpha = start_t[lt] + sem[lt];
    for (int s = 1; s < len; s++) {
        float av[5];
#pragma unroll
        for (int i = 0; i < 5; i++) av[i] = __shfl_sync(0xffffffffu, alpha, i) + trc[i];
        float mx = av[0];
#pragma unroll
        for (int i = 1; i < 5; i++) mx = fmaxf(mx, av[i]);
        float ssum = 0.f;
#pragma unroll
        for (int i = 0; i < 5; i++) ssum += expf(av[i] - mx);
        float an = mx + logf(ssum) + sem[s * Tt + lt];
        if (lane < 5) alpha = an;
    }
    float v = (lane < 5) ? alpha + end_t[lane] : -3.0e38f;
    float mx = v;
#pragma unroll
    for (int o = 16; o; o >>= 1) mx = fmaxf(mx, __shfl_xor_sync(0xffffffffu, mx, o));
    float e = (lane < 5) ? expf(v - mx) : 0.f;
#pragma unroll
    for (int o = 16; o; o >>= 1) e += __shfl_xor_sync(0xffffffffu, e, o);
    if (lane == 0) g_scores[b] = mx + logf(e) - num;
}

__global__ void finish_kernel(float* __restrict__ out)
{
    int t = threadIdx.x;
    float v = g_scores[t] + g_scores[t + 32];
#pragma unroll
    for (int o = 16; o; o >>= 1) v += __shfl_down_sync(0xffffffffu, v, o);
    if (t == 0) out[0] = v * (1.f / 64.f);
}

extern "C" void kernel_launch(void* const* d_in, const int* in_sizes, int n_in,
                              void* d_out, int out_size)
{
    const int*   x       = (const int*)d_in[0];
    const int*   tags    = (const int*)d_in[1];
    const int*   lengths = (const int*)d_in[2];
    const float* emb     = (const float*)d_in[3];
    const float* Wih_f   = (const float*)d_in[4];
    const float* Whh_f   = (const float*)d_in[5];
    const float* b_f     = (const float*)d_in[6];
    const float* Wih_b   = (const float*)d_in[7];
    const float* Whh_b   = (const float*)d_in[8];
    const float* b_b     = (const float*)d_in[9];
    const float* Wlin    = (const float*)d_in[10];
    const float* blin    = (const float*)d_in[11];
    const float* trans   = (const float*)d_in[12];
    const float* start_t = (const float*)d_in[13];
    const float* end_t   = (const float*)d_in[14];
    float* out = (float*)d_out;

    cudaFuncSetAttribute(lstm_kernel,
                         cudaFuncAttributeMaxDynamicSharedMemorySize, LSTM_SMEM);
    cudaFuncSetAttribute(proj_kernel,
                         cudaFuncAttributeMaxDynamicSharedMemorySize, PROJ_SMEM);

    prep_kernel<<<512, 256>>>(x);
    conv_kernel<<<10000, 256>>>(emb, Wih_f, Wih_b);
    proj_kernel<<<dim3(79, 32), 256, PROJ_SMEM>>>(b_f, b_b);
    gather_kernel<<<2 * Ss, 256>>>(x);
    lstm_kernel<<<128, 256, LSTM_SMEM>>>(Whh_f, Whh_b);
    emis_kernel<<<Ss, 320>>>(Wlin, blin);
    crf_kernel<<<Bb, 32>>>(tags, lengths, trans, start_t, end_t);
    finish_kernel<<<1, 32>>>(out);
}